// round 6
// baseline (speedup 1.0000x reference)
#include <cuda_runtime.h>
#include <stdint.h>

#define NB 32768
#define NE 1024

// add on the FMA pipe: d = a*one + b (one==1, opaque runtime value -> IMAD)
static __device__ __forceinline__ uint32_t fadd(uint32_t a, uint32_t b, uint32_t one) {
    uint32_t d;
    asm("mad.lo.u32 %0, %1, %2, %3;" : "=r"(d) : "r"(a), "r"(one), "r"(b));
    return d;
}
#define FADDC(d, a, C) asm("mad.lo.u32 %0, %1, %2, %3;" : "=r"(d) : "r"(a), "r"(one), "n"(C))

static __device__ __forceinline__ uint32_t rotl32(uint32_t x, int r) {
    return __funnelshift_l(x, x, r);
}

// (a | b) ^ c in one LOP3  (LUT (0xF0|0xCC)^0xAA = 0x56)
static __device__ __forceinline__ uint32_t lop3_orxor(uint32_t a, uint32_t b, uint32_t c) {
    uint32_t d;
    asm("lop3.b32 %0, %1, %2, %3, 0x56;" : "=r"(d) : "r"(a), "r"(b), "r"(c));
    return d;
}

// rotate-via-wide-mul (fma pipe, rt~4) + fused or/xor LOP3.
// mul = (1u<<r) * one (opaque) so ptxas can't strength-reduce to shifts.
static __device__ __forceinline__ uint32_t rotw(uint32_t x1, uint32_t x0, uint32_t mul) {
    unsigned long long w;
    asm("mul.wide.u32 %0, %1, %2;" : "=l"(w) : "r"(x1), "r"(mul));
    return lop3_orxor((uint32_t)w, (uint32_t)(w >> 32), x0);
}

// rotate-via-SHF (alu pipe, rt2) + xor LOP3
static __device__ __forceinline__ uint32_t rots(uint32_t x1, uint32_t x0, int r) {
    return rotl32(x1, r) ^ x0;
}

struct RotM { uint32_t m15, m29, m24; };

// threefry2x32, key (0,42), block (0,i); returns x0^x1 after 20 rounds —
// matches jax _threefry_random_bits_partitionable (bit_width=32).
// Caller pre-adds ks1=42 into x1. 7 of 20 rotates go to the fma pipe
// (wide-mul), 13 stay on alu (SHF) — pipe-balanced for sm_103a.
static __device__ __forceinline__ uint32_t tf(uint32_t x1, uint32_t one, const RotM& M) {
    uint32_t x0;
    // group 1 {13,15,26,6}: S W S S
    x0 = x1;                 x1 = rots(x1, x0, 13);
    x0 = fadd(x0, x1, one);  x1 = rotw(x1, x0, M.m15);
    x0 = fadd(x0, x1, one);  x1 = rots(x1, x0, 26);
    x0 = fadd(x0, x1, one);  x1 = rots(x1, x0, 6);
    FADDC(x0, x0, 42u);  FADDC(x1, x1, 0x1BD11BF0u + 1u);
    // group 2 {17,29,16,24}: S W S W
    x0 = fadd(x0, x1, one);  x1 = rots(x1, x0, 17);
    x0 = fadd(x0, x1, one);  x1 = rotw(x1, x0, M.m29);
    x0 = fadd(x0, x1, one);  x1 = rots(x1, x0, 16);
    x0 = fadd(x0, x1, one);  x1 = rotw(x1, x0, M.m24);
    FADDC(x0, x0, 0x1BD11BF0u);  FADDC(x1, x1, 2u);
    // group 3 {13,15,26,6}: S W S S
    x0 = fadd(x0, x1, one);  x1 = rots(x1, x0, 13);
    x0 = fadd(x0, x1, one);  x1 = rotw(x1, x0, M.m15);
    x0 = fadd(x0, x1, one);  x1 = rots(x1, x0, 26);
    x0 = fadd(x0, x1, one);  x1 = rots(x1, x0, 6);
    /* x0 += ks0 (=0) */     FADDC(x1, x1, 45u);
    // group 4 {17,29,16,24}: S W S W
    x0 = fadd(x0, x1, one);  x1 = rots(x1, x0, 17);
    x0 = fadd(x0, x1, one);  x1 = rotw(x1, x0, M.m29);
    x0 = fadd(x0, x1, one);  x1 = rots(x1, x0, 16);
    x0 = fadd(x0, x1, one);  x1 = rotw(x1, x0, M.m24);
    FADDC(x0, x0, 42u);  FADDC(x1, x1, 0x1BD11BF0u + 4u);
    // group 5 {13,15,26,6}: S W S S
    x0 = fadd(x0, x1, one);  x1 = rots(x1, x0, 13);
    x0 = fadd(x0, x1, one);  x1 = rotw(x1, x0, M.m15);
    x0 = fadd(x0, x1, one);  x1 = rots(x1, x0, 26);
    x0 = fadd(x0, x1, one);  x1 = rots(x1, x0, 6);
    FADDC(x0, x0, 0x1BD11BF0u);  FADDC(x1, x1, 5u);
    return x0 ^ x1;
}

__global__ __launch_bounds__(256)
void dnm_kernel(const float4* __restrict__ embeds,
                const float* __restrict__ factors,
                const float4* __restrict__ mask_token,
                float4* __restrict__ out_embeds,
                float4* __restrict__ out_mask,
                uint32_t one) {
    __shared__ uint32_t sh_hist[256];
    __shared__ unsigned long long sh_cand[1040];   // unique keys (m<<10)|col
    __shared__ int sh_cnt;
    __shared__ int sh_k;
    __shared__ int sh_bucket;
    __shared__ int sh_rem;
    __shared__ unsigned long long sh_thr;

    const int row = blockIdx.x;
    const int tid = threadIdx.x;

    RotM M;   // opaque rotate multipliers (uniform regs)
    M.m15 = (1u << 15) * one;
    M.m29 = (1u << 29) * one;
    M.m24 = (1u << 24) * one;

    // Prefetch streaming data; threefry compute hides the latency.
    const float4 e  = embeds[(size_t)row * (NE / 4) + tid];
    const float4 mt = __ldg(&mask_token[tid]);

    sh_hist[tid] = 0u;
    if (tid == 0) {
        sh_cnt = 0;
        const float f = __ldg(&factors[row]);
        int k = (int)floorf(307.2f * f);   // f32(1024*0.3)*factor, floor
        sh_k = k < 1 ? 1 : k;
    }
    __syncthreads();

    // ---- Phase 1: RNG for 4 contiguous columns + fused histogram ---------
    // Score order = (mantissa bits>>9) asc, ties by column asc (stable sort).
    uint32_t m[4];
    const uint32_t base = (uint32_t)(row * NE + tid * 4) + 42u;  // +ks1 baked in
    #pragma unroll
    for (int j = 0; j < 4; j++) {
        const uint32_t bits = tf(base + j, one, M);
        m[j] = bits >> 9;                         // 23-bit mantissa key
        atomicAdd(&sh_hist[m[j] >> 15], 1u);      // bucket = top 8 of 23 bits
    }
    __syncthreads();

    // ---- Phase 2: warp 0 scans 256 bins for the k-th-smallest bucket -----
    if (tid < 32) {
        const int lane = tid;
        uint32_t v[8];
        uint32_t s = 0;
        #pragma unroll
        for (int t = 0; t < 8; t++) { v[t] = sh_hist[lane * 8 + t]; s += v[t]; }
        uint32_t incl = s;
        #pragma unroll
        for (int o = 1; o < 32; o <<= 1) {
            uint32_t n = __shfl_up_sync(0xFFFFFFFFu, incl, o);
            if (lane >= o) incl += n;
        }
        const uint32_t excl = incl - s;
        const uint32_t k = (uint32_t)sh_k;
        if (excl < k && k <= incl) {            // unique lane
            uint32_t c = excl;
            #pragma unroll
            for (int t = 0; t < 8; t++) {
                if (k <= c + v[t]) { sh_bucket = lane * 8 + t; sh_rem = (int)(k - c); break; }
                c += v[t];
            }
        }
    }
    __syncthreads();

    // ---- Phase 3: collect boundary-bucket candidates as unique keys ------
    const uint32_t bkt = (uint32_t)sh_bucket;
    #pragma unroll
    for (int j = 0; j < 4; j++) {
        if ((m[j] >> 15) == bkt) {
            const int p = atomicAdd(&sh_cnt, 1);
            sh_cand[p] = ((unsigned long long)m[j] << 10) | (unsigned)(tid * 4 + j);
        }
    }
    __syncthreads();

    // ---- Phase 4: warp 0 finds the exact k-th smallest key ---------------
    if (tid < 32) {
        const int c = sh_cnt;
        const int rem = sh_rem;
        for (int idx = tid; idx < c; idx += 32) {
            const unsigned long long key = sh_cand[idx];
            int rank = 0;
            for (int j2 = 0; j2 < c; j2++) rank += (sh_cand[j2] < key);
            if (rank == rem - 1) sh_thr = key;   // keys unique -> one writer
        }
    }
    __syncthreads();

    // ---- Phase 5: apply mask (masked <=> (m,col) <= (thrM,thrC) lex) -----
    const unsigned long long thr = sh_thr;
    const uint32_t thrM = (uint32_t)(thr >> 10);
    const uint32_t thrC = (uint32_t)thr & 1023u;
    const uint32_t cbase = (uint32_t)(tid * 4);

    const bool k0 = (m[0] < thrM) || ((m[0] == thrM) && (cbase + 0 <= thrC));
    const bool k1 = (m[1] < thrM) || ((m[1] == thrM) && (cbase + 1 <= thrC));
    const bool k2 = (m[2] < thrM) || ((m[2] == thrM) && (cbase + 2 <= thrC));
    const bool k3 = (m[3] < thrM) || ((m[3] == thrM) && (cbase + 3 <= thrC));

    float4 oe, om;
    oe.x = k0 ? mt.x : e.x;  om.x = k0 ? 0.0f : 1.0f;
    oe.y = k1 ? mt.y : e.y;  om.y = k1 ? 0.0f : 1.0f;
    oe.z = k2 ? mt.z : e.z;  om.z = k2 ? 0.0f : 1.0f;
    oe.w = k3 ? mt.w : e.w;  om.w = k3 ? 0.0f : 1.0f;

    out_embeds[(size_t)row * (NE / 4) + tid] = oe;
    out_mask[(size_t)row * (NE / 4) + tid]   = om;
}

extern "C" void kernel_launch(void* const* d_in, const int* in_sizes, int n_in,
                              void* d_out, int out_size) {
    const float4* embeds = (const float4*)d_in[0];     // [32768, 1024] f32
    const float* factors = (const float*)d_in[1];      // [32768] f32
    const float4* mask_token = (const float4*)d_in[2]; // [1, 1024] f32

    float* out = (float*)d_out;
    float4* out_embeds = (float4*)out;                       // [B, E]
    float4* out_mask = (float4*)(out + (size_t)NB * NE);     // [B, E]

    dnm_kernel<<<NB, 256>>>(embeds, factors, mask_token, out_embeds, out_mask, 1u);
}

// round 7
// speedup vs baseline: 1.5154x; 1.5154x over previous
#include <cuda_runtime.h>
#include <stdint.h>

#define NB 32768
#define NE 1024

// add on the FMA pipe: d = a*one + b (one==1, opaque runtime value -> IMAD)
static __device__ __forceinline__ uint32_t fadd(uint32_t a, uint32_t b, uint32_t one) {
    uint32_t d;
    asm("mad.lo.u32 %0, %1, %2, %3;" : "=r"(d) : "r"(a), "r"(one), "r"(b));
    return d;
}
#define FADDC(d, a, C) asm("mad.lo.u32 %0, %1, %2, %3;" : "=r"(d) : "r"(a), "r"(one), "n"(C))

static __device__ __forceinline__ uint32_t rotl32(uint32_t x, int r) {
    return __funnelshift_l(x, x, r);
}

// (a | b) ^ c in one LOP3  (LUT (0xF0|0xCC)^0xAA = 0x56)
static __device__ __forceinline__ uint32_t lop3_orxor(uint32_t a, uint32_t b, uint32_t c) {
    uint32_t d;
    asm("lop3.b32 %0, %1, %2, %3, 0x56;" : "=r"(d) : "r"(a), "r"(b), "r"(c));
    return d;
}

// rotate on the FMA pipe via two plain 32-bit IMADs (no 64-bit asm pairs):
// lo = x1<<r, hi = x1>>(32-r); (lo|hi)^x0 fused into one LOP3.
// mul = (1u<<r)*one is opaque so ptxas can't strength-reduce to shifts.
static __device__ __forceinline__ uint32_t rotf(uint32_t x1, uint32_t x0, uint32_t mul) {
    const uint32_t lo = x1 * mul;            // IMAD (fma pipe)
    const uint32_t hi = __umulhi(x1, mul);   // IMAD.HI (fma pipe)
    return lop3_orxor(lo, hi, x0);           // 1 alu
}

// rotate on the ALU pipe: SHF + LOP3(xor)
static __device__ __forceinline__ uint32_t rots(uint32_t x1, uint32_t x0, int r) {
    return rotl32(x1, r) ^ x0;
}

struct RotM { uint32_t m15, m26, m29, m24; };

// threefry2x32, key (0,42), block (0,i); returns x0^x1 after 20 rounds —
// matches jax _threefry_random_bits_partitionable (bit_width=32).
// Caller pre-adds ks1=42 into x1. 8 of 20 rotates moved to the fma pipe.
static __device__ __forceinline__ uint32_t tf(uint32_t x1, uint32_t one, const RotM M) {
    uint32_t x0;
    // group 1 {13,15,26,6}: S F F S
    x0 = x1;                 x1 = rots(x1, x0, 13);
    x0 = fadd(x0, x1, one);  x1 = rotf(x1, x0, M.m15);
    x0 = fadd(x0, x1, one);  x1 = rotf(x1, x0, M.m26);
    x0 = fadd(x0, x1, one);  x1 = rots(x1, x0, 6);
    FADDC(x0, x0, 42u);  FADDC(x1, x1, 0x1BD11BF0u + 1u);
    // group 2 {17,29,16,24}: S F S F
    x0 = fadd(x0, x1, one);  x1 = rots(x1, x0, 17);
    x0 = fadd(x0, x1, one);  x1 = rotf(x1, x0, M.m29);
    x0 = fadd(x0, x1, one);  x1 = rots(x1, x0, 16);
    x0 = fadd(x0, x1, one);  x1 = rotf(x1, x0, M.m24);
    FADDC(x0, x0, 0x1BD11BF0u);  FADDC(x1, x1, 2u);
    // group 3 {13,15,26,6}: S F S S
    x0 = fadd(x0, x1, one);  x1 = rots(x1, x0, 13);
    x0 = fadd(x0, x1, one);  x1 = rotf(x1, x0, M.m15);
    x0 = fadd(x0, x1, one);  x1 = rots(x1, x0, 26);
    x0 = fadd(x0, x1, one);  x1 = rots(x1, x0, 6);
    /* x0 += ks0 (=0) */     FADDC(x1, x1, 45u);
    // group 4 {17,29,16,24}: S F S F
    x0 = fadd(x0, x1, one);  x1 = rots(x1, x0, 17);
    x0 = fadd(x0, x1, one);  x1 = rotf(x1, x0, M.m29);
    x0 = fadd(x0, x1, one);  x1 = rots(x1, x0, 16);
    x0 = fadd(x0, x1, one);  x1 = rotf(x1, x0, M.m24);
    FADDC(x0, x0, 42u);  FADDC(x1, x1, 0x1BD11BF0u + 4u);
    // group 5 {13,15,26,6}: S F S S
    x0 = fadd(x0, x1, one);  x1 = rots(x1, x0, 13);
    x0 = fadd(x0, x1, one);  x1 = rotf(x1, x0, M.m15);
    x0 = fadd(x0, x1, one);  x1 = rots(x1, x0, 26);
    x0 = fadd(x0, x1, one);  x1 = rots(x1, x0, 6);
    FADDC(x0, x0, 0x1BD11BF0u);  FADDC(x1, x1, 5u);
    return x0 ^ x1;
}

__global__ __launch_bounds__(256)
void dnm_kernel(const float4* __restrict__ embeds,
                const float* __restrict__ factors,
                const float4* __restrict__ mask_token,
                float4* __restrict__ out_embeds,
                float4* __restrict__ out_mask,
                uint32_t one) {
    __shared__ uint32_t sh_hist[256];
    __shared__ unsigned long long sh_cand[1040];   // unique keys (m<<10)|col
    __shared__ int sh_cnt;
    __shared__ int sh_k;
    __shared__ int sh_bucket;
    __shared__ int sh_rem;
    __shared__ unsigned long long sh_thr;

    const int row = blockIdx.x;
    const int tid = threadIdx.x;

    RotM M;   // opaque rotate multipliers (uniform across the CTA)
    M.m15 = (1u << 15) * one;
    M.m26 = (1u << 26) * one;
    M.m29 = (1u << 29) * one;
    M.m24 = (1u << 24) * one;

    // Prefetch streaming data; threefry compute hides the latency.
    const float4 e  = embeds[(size_t)row * (NE / 4) + tid];
    const float4 mt = __ldg(&mask_token[tid]);

    sh_hist[tid] = 0u;
    if (tid == 0) {
        sh_cnt = 0;
        const float f = __ldg(&factors[row]);
        int k = (int)floorf(307.2f * f);   // f32(1024*0.3)*factor, floor
        sh_k = k < 1 ? 1 : k;
    }
    __syncthreads();

    // ---- Phase 1: RNG for 4 contiguous columns + fused histogram ---------
    // Rank order = (mantissa bits>>9) asc, ties by column asc (stable sort).
    uint32_t m[4];
    const uint32_t base = (uint32_t)(row * NE + tid * 4) + 42u;  // +ks1 baked in
    #pragma unroll
    for (int j = 0; j < 4; j++) {
        const uint32_t bits = tf(base + j, one, M);
        m[j] = bits >> 9;                         // 23-bit mantissa key
        atomicAdd(&sh_hist[m[j] >> 15], 1u);      // bucket = top 8 of 23 bits
    }
    __syncthreads();

    // ---- Phase 2: warp 0 scans 256 bins for the k-th-smallest bucket -----
    if (tid < 32) {
        const int lane = tid;
        uint32_t v[8];
        uint32_t s = 0;
        #pragma unroll
        for (int t = 0; t < 8; t++) { v[t] = sh_hist[lane * 8 + t]; s += v[t]; }
        uint32_t incl = s;
        #pragma unroll
        for (int o = 1; o < 32; o <<= 1) {
            uint32_t n = __shfl_up_sync(0xFFFFFFFFu, incl, o);
            if (lane >= o) incl += n;
        }
        const uint32_t excl = incl - s;
        const uint32_t k = (uint32_t)sh_k;
        if (excl < k && k <= incl) {            // unique lane
            uint32_t c = excl;
            #pragma unroll
            for (int t = 0; t < 8; t++) {
                if (k <= c + v[t]) { sh_bucket = lane * 8 + t; sh_rem = (int)(k - c); break; }
                c += v[t];
            }
        }
    }
    __syncthreads();

    // ---- Phase 3: collect boundary-bucket candidates as unique keys ------
    const uint32_t bkt = (uint32_t)sh_bucket;
    #pragma unroll
    for (int j = 0; j < 4; j++) {
        if ((m[j] >> 15) == bkt) {
            const int p = atomicAdd(&sh_cnt, 1);
            sh_cand[p] = ((unsigned long long)m[j] << 10) | (unsigned)(tid * 4 + j);
        }
    }
    __syncthreads();

    // ---- Phase 4: warp 0 finds the exact k-th smallest key ---------------
    if (tid < 32) {
        const int c = sh_cnt;
        const int rem = sh_rem;
        for (int idx = tid; idx < c; idx += 32) {
            const unsigned long long key = sh_cand[idx];
            int rank = 0;
            for (int j2 = 0; j2 < c; j2++) rank += (sh_cand[j2] < key);
            if (rank == rem - 1) sh_thr = key;   // keys unique -> one writer
        }
    }
    __syncthreads();

    // ---- Phase 5: apply mask (masked <=> (m,col) <= (thrM,thrC) lex) -----
    const unsigned long long thr = sh_thr;
    const uint32_t thrM = (uint32_t)(thr >> 10);
    const uint32_t thrC = (uint32_t)thr & 1023u;
    const uint32_t cbase = (uint32_t)(tid * 4);

    const bool k0 = (m[0] < thrM) || ((m[0] == thrM) && (cbase + 0 <= thrC));
    const bool k1 = (m[1] < thrM) || ((m[1] == thrM) && (cbase + 1 <= thrC));
    const bool k2 = (m[2] < thrM) || ((m[2] == thrM) && (cbase + 2 <= thrC));
    const bool k3 = (m[3] < thrM) || ((m[3] == thrM) && (cbase + 3 <= thrC));

    float4 oe, om;
    oe.x = k0 ? mt.x : e.x;  om.x = k0 ? 0.0f : 1.0f;
    oe.y = k1 ? mt.y : e.y;  om.y = k1 ? 0.0f : 1.0f;
    oe.z = k2 ? mt.z : e.z;  om.z = k2 ? 0.0f : 1.0f;
    oe.w = k3 ? mt.w : e.w;  om.w = k3 ? 0.0f : 1.0f;

    out_embeds[(size_t)row * (NE / 4) + tid] = oe;
    out_mask[(size_t)row * (NE / 4) + tid]   = om;
}

extern "C" void kernel_launch(void* const* d_in, const int* in_sizes, int n_in,
                              void* d_out, int out_size) {
    const float4* embeds = (const float4*)d_in[0];     // [32768, 1024] f32
    const float* factors = (const float*)d_in[1];      // [32768] f32
    const float4* mask_token = (const float4*)d_in[2]; // [1, 1024] f32

    float* out = (float*)d_out;
    float4* out_embeds = (float4*)out;                       // [B, E]
    float4* out_mask = (float4*)(out + (size_t)NB * NE);     // [B, E]

    dnm_kernel<<<NB, 256>>>(embeds, factors, mask_token, out_embeds, out_mask, 1u);
}

// round 8
// speedup vs baseline: 1.7367x; 1.1460x over previous
#include <cuda_runtime.h>
#include <stdint.h>

#define NB 32768
#define NE 1024

// add on the FMA pipe: d = a*one + b (one==1, opaque runtime value -> IMAD)
static __device__ __forceinline__ uint32_t fadd(uint32_t a, uint32_t b, uint32_t one) {
    uint32_t d;
    asm("mad.lo.u32 %0, %1, %2, %3;" : "=r"(d) : "r"(a), "r"(one), "r"(b));
    return d;
}
#define FADDC(d, a, C) asm("mad.lo.u32 %0, %1, %2, %3;" : "=r"(d) : "r"(a), "r"(one), "n"(C))

static __device__ __forceinline__ uint32_t rotl32(uint32_t x, int r) {
    return __funnelshift_l(x, x, r);
}

static __device__ __forceinline__ void prefetch_l2(const void* p) {
    asm volatile("prefetch.global.L2 [%0];" :: "l"(p));
}

// threefry2x32, key (0,42), block (0,i). Returns x0^x1 after 20 rounds —
// matches jax _threefry_random_bits_partitionable (bit_width=32).
// Caller pre-adds ks1=42 into x1. Adds forced to IMAD (fma pipe);
// rotates stay SHF+LOP3 (alu pipe) — R4 form, empirically fastest.
static __device__ __forceinline__ uint32_t tf(uint32_t x1, uint32_t one) {
    uint32_t x0;
    // rounds 1-4 {13,15,26,6}
    x0 = x1;                 x1 = rotl32(x1, 13) ^ x0;
    x0 = fadd(x0, x1, one);  x1 = rotl32(x1, 15) ^ x0;
    x0 = fadd(x0, x1, one);  x1 = rotl32(x1, 26) ^ x0;
    x0 = fadd(x0, x1, one);  x1 = rotl32(x1,  6) ^ x0;
    FADDC(x0, x0, 42u);  FADDC(x1, x1, 0x1BD11BF0u + 1u);
    // rounds 5-8 {17,29,16,24}
    x0 = fadd(x0, x1, one);  x1 = rotl32(x1, 17) ^ x0;
    x0 = fadd(x0, x1, one);  x1 = rotl32(x1, 29) ^ x0;
    x0 = fadd(x0, x1, one);  x1 = rotl32(x1, 16) ^ x0;
    x0 = fadd(x0, x1, one);  x1 = rotl32(x1, 24) ^ x0;
    FADDC(x0, x0, 0x1BD11BF0u);  FADDC(x1, x1, 2u);
    // rounds 9-12 {13,15,26,6}
    x0 = fadd(x0, x1, one);  x1 = rotl32(x1, 13) ^ x0;
    x0 = fadd(x0, x1, one);  x1 = rotl32(x1, 15) ^ x0;
    x0 = fadd(x0, x1, one);  x1 = rotl32(x1, 26) ^ x0;
    x0 = fadd(x0, x1, one);  x1 = rotl32(x1,  6) ^ x0;
    /* x0 += ks0 (=0) */     FADDC(x1, x1, 45u);
    // rounds 13-16 {17,29,16,24}
    x0 = fadd(x0, x1, one);  x1 = rotl32(x1, 17) ^ x0;
    x0 = fadd(x0, x1, one);  x1 = rotl32(x1, 29) ^ x0;
    x0 = fadd(x0, x1, one);  x1 = rotl32(x1, 16) ^ x0;
    x0 = fadd(x0, x1, one);  x1 = rotl32(x1, 24) ^ x0;
    FADDC(x0, x0, 42u);  FADDC(x1, x1, 0x1BD11BF0u + 4u);
    // rounds 17-20 {13,15,26,6}
    x0 = fadd(x0, x1, one);  x1 = rotl32(x1, 13) ^ x0;
    x0 = fadd(x0, x1, one);  x1 = rotl32(x1, 15) ^ x0;
    x0 = fadd(x0, x1, one);  x1 = rotl32(x1, 26) ^ x0;
    x0 = fadd(x0, x1, one);  x1 = rotl32(x1,  6) ^ x0;
    FADDC(x0, x0, 0x1BD11BF0u);  FADDC(x1, x1, 5u);
    return x0 ^ x1;
}

__global__ __launch_bounds__(256, 6)
void dnm_kernel(const float4* __restrict__ embeds,
                const float* __restrict__ factors,
                const float4* __restrict__ mask_token,
                float4* __restrict__ out_embeds,
                float4* __restrict__ out_mask,
                uint32_t one) {
    __shared__ uint32_t sh_hist[256];
    __shared__ unsigned long long sh_cand[1040];   // unique keys (m<<10)|col
    __shared__ int sh_cnt;
    __shared__ int sh_k;
    __shared__ int sh_bucket;
    __shared__ int sh_rem;
    __shared__ unsigned long long sh_thr;

    const int row = blockIdx.x;
    const int tid = threadIdx.x;

    // Warm L2 early without holding destination registers.
    const float4* e_ptr  = embeds + (size_t)row * (NE / 4) + tid;
    const float4* mt_ptr = mask_token + tid;
    prefetch_l2(e_ptr);
    prefetch_l2(mt_ptr);

    sh_hist[tid] = 0u;
    if (tid == 0) {
        sh_cnt = 0;
        const float f = __ldg(&factors[row]);
        int k = (int)floorf(307.2f * f);   // f32(1024*0.3)*factor, floor
        sh_k = k < 1 ? 1 : k;
    }
    __syncthreads();

    // ---- Phase 1: RNG for 4 contiguous columns + fused histogram ---------
    // Rank order = (bits>>9) asc, ties by column asc (stable argsort).
    uint32_t m[4];
    const uint32_t base = (uint32_t)(row * NE + tid * 4) + 42u;  // +ks1 baked in
    #pragma unroll
    for (int j = 0; j < 4; j++) {
        const uint32_t bits = tf(base + j, one);
        m[j] = bits >> 9;                         // 23-bit mantissa key
        atomicAdd(&sh_hist[m[j] >> 15], 1u);      // bucket = top 8 of 23 bits
    }

    // Issue real loads now (L2-resident after prefetch); latency hides
    // behind the two barrier waits + warp-0 phases below.
    const float4 e  = *e_ptr;
    const float4 mt = __ldg(mt_ptr);
    __syncthreads();

    // ---- Phase 2: warp 0 scans 256 bins for the k-th-smallest bucket -----
    if (tid < 32) {
        const int lane = tid;
        uint32_t v[8];
        uint32_t s = 0;
        #pragma unroll
        for (int t = 0; t < 8; t++) { v[t] = sh_hist[lane * 8 + t]; s += v[t]; }
        uint32_t incl = s;
        #pragma unroll
        for (int o = 1; o < 32; o <<= 1) {
            uint32_t n = __shfl_up_sync(0xFFFFFFFFu, incl, o);
            if (lane >= o) incl += n;
        }
        const uint32_t excl = incl - s;
        const uint32_t k = (uint32_t)sh_k;
        if (excl < k && k <= incl) {            // unique lane
            uint32_t c = excl;
            #pragma unroll
            for (int t = 0; t < 8; t++) {
                if (k <= c + v[t]) { sh_bucket = lane * 8 + t; sh_rem = (int)(k - c); break; }
                c += v[t];
            }
        }
    }
    __syncthreads();

    // ---- Phase 3: collect boundary-bucket candidates as unique keys ------
    const uint32_t bkt = (uint32_t)sh_bucket;
    #pragma unroll
    for (int j = 0; j < 4; j++) {
        if ((m[j] >> 15) == bkt) {
            const int p = atomicAdd(&sh_cnt, 1);
            sh_cand[p] = ((unsigned long long)m[j] << 10) | (unsigned)(tid * 4 + j);
        }
    }
    __syncthreads();

    // ---- Phase 4: warp 0 finds the exact k-th smallest key ---------------
    if (tid < 32) {
        const int c = sh_cnt;
        const int rem = sh_rem;
        for (int idx = tid; idx < c; idx += 32) {
            const unsigned long long key = sh_cand[idx];
            int rank = 0;
            for (int j2 = 0; j2 < c; j2++) rank += (sh_cand[j2] < key);
            if (rank == rem - 1) sh_thr = key;   // keys unique -> one writer
        }
    }
    __syncthreads();

    // ---- Phase 5: apply mask (masked <=> (m,col) <= (thrM,thrC) lex) -----
    const unsigned long long thr = sh_thr;
    const uint32_t thrM = (uint32_t)(thr >> 10);
    const uint32_t thrC = (uint32_t)thr & 1023u;
    const uint32_t cbase = (uint32_t)(tid * 4);

    const bool k0 = (m[0] < thrM) || ((m[0] == thrM) && (cbase + 0 <= thrC));
    const bool k1 = (m[1] < thrM) || ((m[1] == thrM) && (cbase + 1 <= thrC));
    const bool k2 = (m[2] < thrM) || ((m[2] == thrM) && (cbase + 2 <= thrC));
    const bool k3 = (m[3] < thrM) || ((m[3] == thrM) && (cbase + 3 <= thrC));

    float4 oe, om;
    oe.x = k0 ? mt.x : e.x;  om.x = k0 ? 0.0f : 1.0f;
    oe.y = k1 ? mt.y : e.y;  om.y = k1 ? 0.0f : 1.0f;
    oe.z = k2 ? mt.z : e.z;  om.z = k2 ? 0.0f : 1.0f;
    oe.w = k3 ? mt.w : e.w;  om.w = k3 ? 0.0f : 1.0f;

    out_embeds[(size_t)row * (NE / 4) + tid] = oe;
    out_mask[(size_t)row * (NE / 4) + tid]   = om;
}

extern "C" void kernel_launch(void* const* d_in, const int* in_sizes, int n_in,
                              void* d_out, int out_size) {
    const float4* embeds = (const float4*)d_in[0];     // [32768, 1024] f32
    const float* factors = (const float*)d_in[1];      // [32768] f32
    const float4* mask_token = (const float4*)d_in[2]; // [1, 1024] f32

    float* out = (float*)d_out;
    float4* out_embeds = (float4*)out;                       // [B, E]
    float4* out_mask = (float4*)(out + (size_t)NB * NE);     // [B, E]

    dnm_kernel<<<NB, 256>>>(embeds, factors, mask_token, out_embeds, out_mask, 1u);
}